// round 15
// baseline (speedup 1.0000x reference)
#include <cuda_runtime.h>
#include <math.h>

// SetConv2dEncoder via Gaussian product factorization (two-kernel design):
//   out[b,k,i,j] = C(i,j) * G[b,k,i+j],  C = exp(-(xi-xj)^2/(4 s2)),
//   G[b,k,s]     = sum_n zc[b,n,k] * exp(-(p_s - u_n)^2 / s2)
// kernel_G: warp-compacted G build (256 blocks) + header write.
// kernel_out: 1 row x half-the-channels per block (8192 blocks), balanced
// 9/9 store chains. Empirical optimum of the split sweep (2/1/half/quarter).

#define S_PAD   2048
#define NCH     17
#define EPS_DEN 1e-8f

// 4 batches x 4 rotations x 17 ch x 2048: copy r holds G[s] at index s-r.
__device__ __align__(16) float g_G4[4 * 4 * NCH * S_PAD];

// ---------------------------------------------------------------------------
// Kernel A: block = 32 consecutive s (lane = s), 8 warps split n.
// Phase 1: order-preserving ballot compaction (~16% of n active).
// Phase 2: dense 17-channel accumulation; smem reduce; 4 rotated copies.
// Block (0,0) also writes the leading x_grid header.
// ---------------------------------------------------------------------------
__global__ void __launch_bounds__(256) kernel_G(
    const float* __restrict__ xz, const float* __restrict__ z,
    const float* __restrict__ x_grid, const float* __restrict__ log_scale,
    float* __restrict__ out, int n, int m, int header)
{
    const int S    = 2 * m - 1;
    const int t    = threadIdx.x;
    const int lane = t & 31;
    const int w    = t >> 5;
    const int bb   = blockIdx.y;
    const int sb   = blockIdx.x * 32;

    if (blockIdx.x == 0 && bb == 0 && header > 0) {
        for (int x = t; x < header; x += 256) out[x - header] = x_grid[x];
    }

    const int s  = sb + lane;
    const int se = (s < S) ? s : (S - 1);
    const int s0 = se >> 1;

    const float s2     = __expf(2.0f * log_scale[0]);
    const float inv_s2 = 1.0f / s2;
    const float p      = 0.5f * (x_grid[s0] + x_grid[se - s0]);

    // block-wide acceptance window: [p(sb)-r, p(sb+31)+r], r = sqrt(80*s2)
    const float x0   = x_grid[0];
    const float step = (x_grid[m - 1] - x0) / (float)(m - 1);
    const float r    = sqrtf(80.0f * s2) + fabsf(step);
    const int   shi  = (sb + 31 < S) ? sb + 31 : S - 1;
    const float lo   = x0 + 0.5f * (float)sb  * step - r;
    const float hi   = x0 + 0.5f * (float)shi * step + r;

    __shared__ float su[8][132];
    __shared__ int   sn[8][132];
    __shared__ float red[8][32][NCH];

    const float* __restrict__ xzb = xz + (size_t)bb * n;
    const float* __restrict__ zb  = z  + (size_t)bb * n * 16;

    // ---- phase 1: compact this warp's n-chunk (order-preserving) ----
    const int nc = n >> 3;
    const int n0 = w * nc;
    int cnt = 0;
    for (int base = 0; base < nc; base += 32) {
        const int  nn  = n0 + base + lane;
        const float u  = __ldg(xzb + nn);
        const bool act = (u >= lo) && (u <= hi);
        const unsigned mask = __ballot_sync(0xffffffffu, act);
        if (act) {
            int pos = cnt + __popc(mask & ((1u << lane) - 1u));
            su[w][pos] = u;
            sn[w][pos] = nn;
        }
        cnt += __popc(mask);
    }

    // ---- phase 2: dense accumulation over compacted list ----
    float acc[NCH];
#pragma unroll
    for (int k = 0; k < NCH; k++) acc[k] = 0.0f;

    for (int idx = 0; idx < cnt; idx++) {
        const float u  = su[w][idx];            // warp-uniform LDS
        const int   nn = sn[w][idx];
        const float d  = p - u;
        const float e  = __expf(-d * d * inv_s2);
        const float4* zr = (const float4*)(zb + ((size_t)nn << 4));
        const float4 z0 = zr[0], z1 = zr[1], z2 = zr[2], z3 = zr[3];
        acc[0]  += e;
        acc[1]  += e * z0.x; acc[2]  += e * z0.y; acc[3]  += e * z0.z; acc[4]  += e * z0.w;
        acc[5]  += e * z1.x; acc[6]  += e * z1.y; acc[7]  += e * z1.z; acc[8]  += e * z1.w;
        acc[9]  += e * z2.x; acc[10] += e * z2.y; acc[11] += e * z2.z; acc[12] += e * z2.w;
        acc[13] += e * z3.x; acc[14] += e * z3.y; acc[15] += e * z3.z; acc[16] += e * z3.w;
    }

#pragma unroll
    for (int k = 0; k < NCH; k++) red[w][lane][k] = acc[k];
    __syncthreads();

    for (int idx = t; idx < 32 * NCH; idx += 256) {
        const int ln = idx & 31, k = idx >> 5;
        const int ss = sb + ln;
        if (ss < S) {
            float v = 0.0f;
#pragma unroll
            for (int ww = 0; ww < 8; ww++) v += red[ww][ln][k];
            float* Gb = g_G4 + (size_t)bb * 4 * NCH * S_PAD;
#pragma unroll
            for (int rr = 0; rr < 4; rr++) {
                const int x = ss - rr;
                if (x >= 0) Gb[(rr * NCH + k) * S_PAD + x] = v;
            }
        }
    }
}

// ---------------------------------------------------------------------------
// Kernel B: block = (row i, channel-half h, batch), balanced 9/9 stores.
// half 0: ch0 (identity), ch1 (density), ch2..8.  half 1: ch9..17.
// Thread t owns j = 4t..4t+3. Rotation copy (i&3) -> aligned LDG.128.
// ---------------------------------------------------------------------------
__global__ void __launch_bounds__(256) kernel_out(
    const float* __restrict__ x_grid, const float* __restrict__ log_scale,
    float* __restrict__ out, int m)
{
    const int i  = blockIdx.x;
    const int h  = blockIdx.y & 1;
    const int bb = blockIdx.y >> 1;
    const int t  = threadIdx.x;
    const int j0 = t << 2;

    const float  xi = x_grid[i];
    const float4 xj = ((const float4*)x_grid)[t];
    const float  inv4s2 = 0.25f / __expf(2.0f * log_scale[0]);

    float dx, c0, c1, c2, c3;
    dx = xi - xj.x; c0 = __expf(-dx * dx * inv4s2);
    dx = xi - xj.y; c1 = __expf(-dx * dx * inv4s2);
    dx = xi - xj.z; c2 = __expf(-dx * dx * inv4s2);
    dx = xi - xj.w; c3 = __expf(-dx * dx * inv4s2);

    const int ri = i & 3;
    const float* __restrict__ G =
        g_G4 + ((size_t)(bb * 4 + ri) * NCH) * S_PAD + (i - ri) + j0;

    const size_t chs = (size_t)m * m;
    float* op = out + (((size_t)bb * 18) * m + i) * m + j0;

    float4 v;
    if (h == 0) {
        // ch0: identity
        v.x = (j0     == i) ? 1.0f : 0.0f;
        v.y = (j0 + 1 == i) ? 1.0f : 0.0f;
        v.z = (j0 + 2 == i) ? 1.0f : 0.0f;
        v.w = (j0 + 3 == i) ? 1.0f : 0.0f;
        __stcs((float4*)op, v);
    }

    // density = C * G0 (both halves need it for the quotient factors)
    const float4 g0 = __ldg((const float4*)G);
    float d0 = c0 * g0.x, d1 = c1 * g0.y, d2 = c2 * g0.z, d3 = c3 * g0.w;

    if (h == 0) {
        v.x = d0; v.y = d1; v.z = d2; v.w = d3;
        __stcs((float4*)(op + chs), v);
    }

    float q0 = __fdividef(c0, d0 + EPS_DEN);
    float q1 = __fdividef(c1, d1 + EPS_DEN);
    float q2 = __fdividef(c2, d2 + EPS_DEN);
    float q3 = __fdividef(c3, d3 + EPS_DEN);

    // balanced chains: h0 -> k=1..7 (7 stores, +2 fixed = 9), h1 -> k=8..16 (9)
    const int k0 = (h == 0) ? 1 : 8;
    const int k1 = (h == 0) ? 8 : NCH;
#pragma unroll
    for (int k = k0; k < k1; k++) {
        const float4 gk = __ldg((const float4*)(G + k * S_PAD));
        v.x = gk.x * q0;
        v.y = gk.y * q1;
        v.z = gk.z * q2;
        v.w = gk.w * q3;
        __stcs((float4*)(op + (size_t)(k + 1) * chs), v);
    }
}

// ---------------------------------------------------------------------------
extern "C" void kernel_launch(void* const* d_in, const int* in_sizes, int n_in,
                              void* d_out, int out_size)
{
    const float* xz        = (const float*)d_in[0];
    const float* z         = (const float*)d_in[1];
    const float* x_grid    = (const float*)d_in[2];
    const float* log_scale = (const float*)d_in[3];

    const int m = in_sizes[2];
    const long long xz_sz = in_sizes[0];
    const long long z_sz  = in_sizes[1];
    const int c = (int)(z_sz / xz_sz);                        // 16
    const long long per_b = (long long)(c + 2) * m * m;       // 18*m*m
    const long long b     = (long long)out_size / per_b;      // 4
    const long long header = (long long)out_size - b * per_b; // leading x_grid
    const int n = (int)(xz_sz / b);

    float* outp = (float*)d_out + header;      // header written by kernel_G

    const int S = 2 * m - 1;
    dim3 gA((unsigned)((S + 31) / 32), (unsigned)b);
    kernel_G<<<gA, 256>>>(xz, z, x_grid, log_scale, outp, n, m, (int)header);

    dim3 gB((unsigned)m, (unsigned)(2 * b));   // 1024 x 8: row x (half, batch)
    kernel_out<<<gB, 256>>>(x_grid, log_scale, outp, m);
}

// round 16
// speedup vs baseline: 1.0322x; 1.0322x over previous
#include <cuda_runtime.h>
#include <math.h>

// SetConv2dEncoder via Gaussian product factorization (two-kernel design):
//   out[b,k,i,j] = C(i,j) * G[b,k,i+j],  C = exp(-(xi-xj)^2/(4 s2)),
//   G[b,k,s]     = sum_n zc[b,n,k] * exp(-(p_s - u_n)^2 / s2)
// kernel_G: warp-compacted G build (256 blocks) + header write.
// kernel_out: 1 row x half-the-channels per block (8192 blocks).
// This is the measured optimum (53.7us) of the full design sweep:
//   row-split {2,1,1/2,1/4}, fusion, PDL, thread counts — all else regressed.
// Streamer runs at ~6.5 TB/s effective stores (~82% of HBM spec): roofline.

#define S_PAD   2048
#define NCH     17
#define EPS_DEN 1e-8f

// 4 batches x 4 rotations x 17 ch x 2048: copy r holds G[s] at index s-r.
__device__ __align__(16) float g_G4[4 * 4 * NCH * S_PAD];

// ---------------------------------------------------------------------------
// Kernel A: block = 32 consecutive s (lane = s), 8 warps split n.
// Phase 1: order-preserving ballot compaction of points inside the block's
// Gaussian window (~16% of n). Phase 2: dense 17-channel accumulation over
// the compacted list. smem reduce across warps, write 4 rotated copies.
// Block (0,0) also writes the leading x_grid header.
// ---------------------------------------------------------------------------
__global__ void __launch_bounds__(256) kernel_G(
    const float* __restrict__ xz, const float* __restrict__ z,
    const float* __restrict__ x_grid, const float* __restrict__ log_scale,
    float* __restrict__ out, int n, int m, int header)
{
    const int S    = 2 * m - 1;
    const int t    = threadIdx.x;
    const int lane = t & 31;
    const int w    = t >> 5;
    const int bb   = blockIdx.y;
    const int sb   = blockIdx.x * 32;

    if (blockIdx.x == 0 && bb == 0 && header > 0) {
        for (int x = t; x < header; x += 256) out[x - header] = x_grid[x];
    }

    const int s  = sb + lane;
    const int se = (s < S) ? s : (S - 1);
    const int s0 = se >> 1;

    const float s2     = __expf(2.0f * log_scale[0]);
    const float inv_s2 = 1.0f / s2;
    const float p      = 0.5f * (x_grid[s0] + x_grid[se - s0]);

    // block-wide acceptance window: [p(sb)-r, p(sb+31)+r], r = sqrt(80*s2)
    const float x0   = x_grid[0];
    const float step = (x_grid[m - 1] - x0) / (float)(m - 1);
    const float r    = sqrtf(80.0f * s2) + fabsf(step);
    const int   shi  = (sb + 31 < S) ? sb + 31 : S - 1;
    const float lo   = x0 + 0.5f * (float)sb  * step - r;
    const float hi   = x0 + 0.5f * (float)shi * step + r;

    __shared__ float su[8][132];
    __shared__ int   sn[8][132];
    __shared__ float red[8][32][NCH];

    const float* __restrict__ xzb = xz + (size_t)bb * n;
    const float* __restrict__ zb  = z  + (size_t)bb * n * 16;

    // ---- phase 1: compact this warp's n-chunk (order-preserving) ----
    const int nc = n >> 3;
    const int n0 = w * nc;
    int cnt = 0;
    for (int base = 0; base < nc; base += 32) {
        const int  nn  = n0 + base + lane;
        const float u  = __ldg(xzb + nn);
        const bool act = (u >= lo) && (u <= hi);
        const unsigned mask = __ballot_sync(0xffffffffu, act);
        if (act) {
            int pos = cnt + __popc(mask & ((1u << lane) - 1u));
            su[w][pos] = u;
            sn[w][pos] = nn;
        }
        cnt += __popc(mask);
    }

    // ---- phase 2: dense accumulation over compacted list ----
    float acc[NCH];
#pragma unroll
    for (int k = 0; k < NCH; k++) acc[k] = 0.0f;

    for (int idx = 0; idx < cnt; idx++) {
        const float u  = su[w][idx];            // warp-uniform LDS
        const int   nn = sn[w][idx];
        const float d  = p - u;
        const float e  = __expf(-d * d * inv_s2);
        const float4* zr = (const float4*)(zb + ((size_t)nn << 4));
        const float4 z0 = zr[0], z1 = zr[1], z2 = zr[2], z3 = zr[3];
        acc[0]  += e;
        acc[1]  += e * z0.x; acc[2]  += e * z0.y; acc[3]  += e * z0.z; acc[4]  += e * z0.w;
        acc[5]  += e * z1.x; acc[6]  += e * z1.y; acc[7]  += e * z1.z; acc[8]  += e * z1.w;
        acc[9]  += e * z2.x; acc[10] += e * z2.y; acc[11] += e * z2.z; acc[12] += e * z2.w;
        acc[13] += e * z3.x; acc[14] += e * z3.y; acc[15] += e * z3.z; acc[16] += e * z3.w;
    }

#pragma unroll
    for (int k = 0; k < NCH; k++) red[w][lane][k] = acc[k];
    __syncthreads();

    for (int idx = t; idx < 32 * NCH; idx += 256) {
        const int ln = idx & 31, k = idx >> 5;
        const int ss = sb + ln;
        if (ss < S) {
            float v = 0.0f;
#pragma unroll
            for (int ww = 0; ww < 8; ww++) v += red[ww][ln][k];
            float* Gb = g_G4 + (size_t)bb * 4 * NCH * S_PAD;
#pragma unroll
            for (int rr = 0; rr < 4; rr++) {
                const int x = ss - rr;
                if (x >= 0) Gb[(rr * NCH + k) * S_PAD + x] = v;
            }
        }
    }
}

// ---------------------------------------------------------------------------
// Kernel B: block = (row i, channel-half h, batch). half 0: ch0 (identity),
// ch1 (density), ch2..9. half 1: ch10..17. Thread t owns j = 4t..4t+3.
// Rotation copy (i&3) -> every per-channel G read is one aligned LDG.128.
// ---------------------------------------------------------------------------
__global__ void __launch_bounds__(256) kernel_out(
    const float* __restrict__ x_grid, const float* __restrict__ log_scale,
    float* __restrict__ out, int m)
{
    const int i  = blockIdx.x;
    const int h  = blockIdx.y & 1;
    const int bb = blockIdx.y >> 1;
    const int t  = threadIdx.x;
    const int j0 = t << 2;

    const float  xi = x_grid[i];
    const float4 xj = ((const float4*)x_grid)[t];
    const float  inv4s2 = 0.25f / __expf(2.0f * log_scale[0]);

    float dx, c0, c1, c2, c3;
    dx = xi - xj.x; c0 = __expf(-dx * dx * inv4s2);
    dx = xi - xj.y; c1 = __expf(-dx * dx * inv4s2);
    dx = xi - xj.z; c2 = __expf(-dx * dx * inv4s2);
    dx = xi - xj.w; c3 = __expf(-dx * dx * inv4s2);

    const int ri = i & 3;
    const float* __restrict__ G =
        g_G4 + ((size_t)(bb * 4 + ri) * NCH) * S_PAD + (i - ri) + j0;

    const size_t chs = (size_t)m * m;
    float* op = out + (((size_t)bb * 18) * m + i) * m + j0;

    float4 v;
    if (h == 0) {
        // ch0: identity
        v.x = (j0     == i) ? 1.0f : 0.0f;
        v.y = (j0 + 1 == i) ? 1.0f : 0.0f;
        v.z = (j0 + 2 == i) ? 1.0f : 0.0f;
        v.w = (j0 + 3 == i) ? 1.0f : 0.0f;
        __stcs((float4*)op, v);
    }

    // density = C * G0 (both halves need it for the quotient factors)
    const float4 g0 = __ldg((const float4*)G);
    float d0 = c0 * g0.x, d1 = c1 * g0.y, d2 = c2 * g0.z, d3 = c3 * g0.w;

    if (h == 0) {
        v.x = d0; v.y = d1; v.z = d2; v.w = d3;
        __stcs((float4*)(op + chs), v);
    }

    float q0 = __fdividef(c0, d0 + EPS_DEN);
    float q1 = __fdividef(c1, d1 + EPS_DEN);
    float q2 = __fdividef(c2, d2 + EPS_DEN);
    float q3 = __fdividef(c3, d3 + EPS_DEN);

    const int k0 = (h == 0) ? 1 : 9;
#pragma unroll 8
    for (int k = k0; k < k0 + 8; k++) {
        const float4 gk = __ldg((const float4*)(G + k * S_PAD));
        v.x = gk.x * q0;
        v.y = gk.y * q1;
        v.z = gk.z * q2;
        v.w = gk.w * q3;
        __stcs((float4*)(op + (size_t)(k + 1) * chs), v);
    }
}

// ---------------------------------------------------------------------------
extern "C" void kernel_launch(void* const* d_in, const int* in_sizes, int n_in,
                              void* d_out, int out_size)
{
    const float* xz        = (const float*)d_in[0];
    const float* z         = (const float*)d_in[1];
    const float* x_grid    = (const float*)d_in[2];
    const float* log_scale = (const float*)d_in[3];

    const int m = in_sizes[2];
    const long long xz_sz = in_sizes[0];
    const long long z_sz  = in_sizes[1];
    const int c = (int)(z_sz / xz_sz);                        // 16
    const long long per_b = (long long)(c + 2) * m * m;       // 18*m*m
    const long long b     = (long long)out_size / per_b;      // 4
    const long long header = (long long)out_size - b * per_b; // leading x_grid
    const int n = (int)(xz_sz / b);

    float* outp = (float*)d_out + header;      // header written by kernel_G

    const int S = 2 * m - 1;
    dim3 gA((unsigned)((S + 31) / 32), (unsigned)b);
    kernel_G<<<gA, 256>>>(xz, z, x_grid, log_scale, outp, n, m, (int)header);

    dim3 gB((unsigned)m, (unsigned)(2 * b));   // 1024 x 8: row x (half, batch)
    kernel_out<<<gB, 256>>>(x_grid, log_scale, outp, m);
}